// round 3
// baseline (speedup 1.0000x reference)
#include <cuda_runtime.h>
#include <math.h>

#define S_LEN 256
#define BATCH 64
#define VOCAB 10000
#define EDIM  512
#define HDIM  1024

typedef unsigned long long u64;

// ---------------- packed fp32x2 helpers (sm_103a FFMA2) ----------------
__device__ __forceinline__ u64 pack2(float lo, float hi) {
    u64 r; asm("mov.b64 %0,{%1,%2};" : "=l"(r) : "f"(lo), "f"(hi)); return r;
}
__device__ __forceinline__ float2 unpack2(u64 v) {
    float2 f; asm("mov.b64 {%0,%1},%2;" : "=f"(f.x), "=f"(f.y) : "l"(v)); return f;
}
__device__ __forceinline__ void ffma2(u64 &c, u64 a, u64 b) {
    asm("fma.rn.f32x2 %0,%1,%2,%0;" : "+l"(c) : "l"(a), "l"(b));
}

// ---------------- scratch (static device memory; no allocations) -------
__device__ float g_W0X[512 * 3072];        // [Wr0_x | Wz0_x | Wh0_x]
__device__ float g_W0A[1024 * 2048];       // [Wr0_h | Wz0_h]
__device__ float g_W0B[1024 * 1024];       // Wh0_h
__device__ float g_W1A[2048 * 3072];       // [Wr1 | Wz1 | Wh1_x(pad0)]
__device__ float g_W1B[1024 * 1024];       // Wh1_h
__device__ float g_bias[6 * 1024];
__device__ float g_xpre[(size_t)16384 * 3072];  // layer0 x-side preacts
__device__ float g_top[(size_t)16384 * 1024];   // layer1 outputs per step
__device__ float g_cat[64 * 2048];         // [h0 | h1] per batch row
__device__ float g_rh[64 * 1024];
__device__ float g_z[64 * 1024];
__device__ float g_xh1[64 * 1024];
__device__ float g_part[589824];           // split-K partials (max 3*64*3072)
__device__ int   g_barcnt;
__device__ int   g_bargen;

// ---------------- grid-wide barrier (148 co-resident CTAs) -------------
__device__ __forceinline__ void grid_bar(int &gen) {
    __syncthreads();
    if (threadIdx.x == 0) {
        __threadfence();
        if (atomicAdd(&g_barcnt, 1) == (int)gridDim.x - 1) {
            atomicExch(&g_barcnt, 0);
            __threadfence();
            atomicAdd(&g_bargen, 1);
        } else {
            volatile int* vg = &g_bargen;
            while (*vg - gen <= 0) { }
        }
        __threadfence();
    }
    gen++;
    __syncthreads();
}

// ---------------- weight repack + state init ---------------------------
__global__ void k_prep(const float* __restrict__ hidden,
                       const float* __restrict__ Wr0, const float* __restrict__ Wz0,
                       const float* __restrict__ Wh0,
                       const float* __restrict__ Wr1, const float* __restrict__ Wz1,
                       const float* __restrict__ Wh1,
                       const float* __restrict__ br0, const float* __restrict__ bz0,
                       const float* __restrict__ bh0,
                       const float* __restrict__ br1, const float* __restrict__ bz1,
                       const float* __restrict__ bh1) {
    int i = blockIdx.x * blockDim.x + threadIdx.x;
    if (i < 512 * 3072) {
        int k = i / 3072, n = i % 3072;
        float v = (n < 1024) ? Wr0[k * 1024 + n]
                : (n < 2048) ? Wz0[k * 1024 + n - 1024]
                             : Wh0[k * 1024 + n - 2048];
        g_W0X[i] = v;
    }
    if (i < 1024 * 2048) {
        int k = i / 2048, n = i % 2048;
        g_W0A[i] = (n < 1024) ? Wr0[(512 + k) * 1024 + n]
                              : Wz0[(512 + k) * 1024 + n - 1024];
    }
    if (i < 1024 * 1024) {
        int k = i >> 10, n = i & 1023;
        g_W0B[i] = Wh0[(512 + k) * 1024 + n];
        g_W1B[i] = Wh1[(1024 + k) * 1024 + n];
    }
    if (i < 2048 * 3072) {
        int k = i / 3072, n = i % 3072;
        float v;
        if (n < 1024)      v = Wr1[k * 1024 + n];
        else if (n < 2048) v = Wz1[k * 1024 + n - 1024];
        else               v = (k < 1024) ? Wh1[k * 1024 + (n - 2048)] : 0.f;
        g_W1A[i] = v;
    }
    if (i < 1024) {
        g_bias[i]        = br0[i]; g_bias[1024 + i] = bz0[i]; g_bias[2048 + i] = bh0[i];
        g_bias[3072 + i] = br1[i]; g_bias[4096 + i] = bz1[i]; g_bias[5120 + i] = bh1[i];
    }
    if (i < 64 * 2048) {
        int b = i >> 11, j = i & 2047;
        g_cat[i] = (j < 1024) ? hidden[b * 1024 + j]
                              : hidden[65536 + b * 1024 + (j - 1024)];
    }
}

// ---------------- 64x64 tile GEMM core (FFMA2, A pre-duplicated) -------
template <bool CGA, bool GATHER>
__device__ __forceinline__ void mm64_core(
    const float* __restrict__ A, int lda,
    const float* __restrict__ Emb, const int* __restrict__ tokens, int m0,
    const float* __restrict__ B, int ldb, int n0, int Nvalid,
    int kbeg, int kend, u64 acc[4][2]) {
    __shared__ __align__(16) u64 As2[64][33];
    __shared__ __align__(16) float Bs[32][64];
    __shared__ int s_tok[64];
    const int tid = threadIdx.x;
    if (GATHER) {
        if (tid < 64) s_tok[tid] = tokens[m0 + tid];
        __syncthreads();
    }
    const int tx = tid & 15, ty = tid >> 4;
    for (int k0 = kbeg; k0 < kend; k0 += 32) {
#pragma unroll
        for (int i = 0; i < 8; i++) {
            int idx = tid + i * 256;
            int kk = idx & 31, mm = idx >> 5;
            int kg = k0 + kk;
            float v = 0.f;
            if (kg < kend) {
                if (GATHER)   v = Emb[(size_t)s_tok[mm] * EDIM + kg];
                else if (CGA) v = __ldcg(&A[(size_t)(m0 + mm) * lda + kg]);
                else          v = A[(size_t)(m0 + mm) * lda + kg];
            }
            As2[mm][kk] = pack2(v, v);
        }
#pragma unroll
        for (int i = 0; i < 8; i++) {
            int idx = tid + i * 256;
            int kk = idx >> 6, nn = idx & 63;
            int kg = k0 + kk, ng = n0 + nn;
            float v = 0.f;
            if (kg < kend && ng < Nvalid) v = B[(size_t)kg * ldb + ng];
            Bs[kk][nn] = v;
        }
        __syncthreads();
#pragma unroll
        for (int k = 0; k < 32; k++) {
            u64 b0 = *(const u64*)&Bs[k][tx * 4];
            u64 b1 = *(const u64*)&Bs[k][tx * 4 + 2];
#pragma unroll
            for (int i = 0; i < 4; i++) {
                u64 a2 = As2[ty * 4 + i][k];
                ffma2(acc[i][0], a2, b0);
                ffma2(acc[i][1], a2, b1);
            }
        }
        __syncthreads();
    }
}

// ---------------- layer0 x-side precompute (gathered GEMM) -------------
__global__ __launch_bounds__(256) void k_embed(const int* __restrict__ inputs,
                                               const float* __restrict__ Emb) {
    u64 acc[4][2] = {};
    int n0 = blockIdx.x * 64, m0 = blockIdx.y * 64;
    mm64_core<false, true>(nullptr, 0, Emb, inputs, m0, g_W0X, 3072, n0, 3072, 0, 512, acc);
    int tx = threadIdx.x & 15, ty = threadIdx.x >> 4;
#pragma unroll
    for (int i = 0; i < 4; i++)
#pragma unroll
        for (int jj = 0; jj < 2; jj++) {
            float2 v = unpack2(acc[i][jj]);
            size_t row = m0 + ty * 4 + i;
            int col = n0 + tx * 4 + jj * 2;
            g_xpre[row * 3072 + col]     = v.x;
            g_xpre[row * 3072 + col + 1] = v.y;
        }
}

// ---------------- split-K partial GEMM inside persistent kernel --------
__device__ __forceinline__ void phase_gemm(const float* A, int lda,
                                           const float* B, int ldb, int N,
                                           int ntile, int sp, int kbeg, int kend) {
    u64 acc[4][2] = {};
    int n0 = ntile * 64;
    mm64_core<true, false>(A, lda, nullptr, nullptr, 0, B, ldb, n0, N, kbeg, kend, acc);
    float* part = g_part + (size_t)sp * 64 * N;
    int tx = threadIdx.x & 15, ty = threadIdx.x >> 4;
#pragma unroll
    for (int i = 0; i < 4; i++)
#pragma unroll
        for (int jj = 0; jj < 2; jj++) {
            float2 v = unpack2(acc[i][jj]);
            int r = ty * 4 + i;
            int c = n0 + tx * 4 + jj * 2;
            part[(size_t)r * N + c]     = v.x;
            part[(size_t)r * N + c + 1] = v.y;
        }
}

__device__ __forceinline__ float sigm(float x) { return 1.f / (1.f + expf(-x)); }

// ---------------- persistent recurrent kernel --------------------------
__global__ __launch_bounds__(256) void k_rec_persist() {
    const int cta = blockIdx.x, tid = threadIdx.x;
    const int gtid = cta * 256 + tid;
    const int nthr = (int)gridDim.x * 256;
    int gen = *(volatile int*)&g_bargen;

    for (int s = 0; s < S_LEN; s++) {
        const int sb = s * BATCH;
        // ---- Phase A: h0 @ [Wr0_h|Wz0_h]  (N=2048, split=4) ----
        if (cta < 128) {
            int nt = cta & 31, sp = cta >> 5;
            phase_gemm(g_cat, 2048, g_W0A, 2048, 2048, nt, sp, sp * 256, sp * 256 + 256);
        }
        grid_bar(gen);
        for (int e = gtid; e < 131072; e += nthr) {
            int r = e >> 11, n = e & 2047;
            float sum = 0.f;
#pragma unroll
            for (int sp = 0; sp < 4; sp++) sum += __ldcg(&g_part[sp * 131072 + e]);
            if (n < 1024) {
                float pre = sum + g_xpre[(size_t)(sb + r) * 3072 + n] + g_bias[n];
                g_rh[r * 1024 + n] = sigm(pre) * __ldcg(&g_cat[r * 2048 + n]);
            } else {
                int j = n - 1024;
                float pre = sum + g_xpre[(size_t)(sb + r) * 3072 + 1024 + j] + g_bias[1024 + j];
                g_z[r * 1024 + j] = sigm(pre);
            }
        }
        grid_bar(gen);
        // ---- Phase B: (r*h0) @ Wh0_h  (N=1024, split=8) ----
        if (cta < 128) {
            int nt = cta & 15, sp = cta >> 4;
            phase_gemm(g_rh, 1024, g_W0B, 1024, 1024, nt, sp, sp * 128, sp * 128 + 128);
        }
        grid_bar(gen);
        for (int e = gtid; e < 65536; e += nthr) {
            int r = e >> 10, n = e & 1023;
            float sum = 0.f;
#pragma unroll
            for (int sp = 0; sp < 8; sp++) sum += __ldcg(&g_part[sp * 65536 + e]);
            float pre = sum + g_xpre[(size_t)(sb + r) * 3072 + 2048 + n] + g_bias[2048 + n];
            float hh = tanhf(pre);
            float z = __ldcg(&g_z[e]);
            float h = __ldcg(&g_cat[r * 2048 + n]);
            g_cat[r * 2048 + n] = (1.f - z) * h + z * hh;
        }
        grid_bar(gen);
        // ---- Phase C: [h0new|h1] @ [Wr1|Wz1|Wh1_x]  (N=3072, split=3) ----
        if (cta < 144) {
            int nt = cta % 48, sp = cta / 48;
            int kb = sp * 704, ke = min(2048, kb + 704);
            phase_gemm(g_cat, 2048, g_W1A, 3072, 3072, nt, sp, kb, ke);
        }
        grid_bar(gen);
        for (int e = gtid; e < 196608; e += nthr) {
            int r = e / 3072, n = e - r * 3072;
            float sum = 0.f;
#pragma unroll
            for (int sp = 0; sp < 3; sp++) sum += __ldcg(&g_part[sp * 196608 + e]);
            if (n < 1024) {
                float pre = sum + g_bias[3072 + n];
                g_rh[r * 1024 + n] = sigm(pre) * __ldcg(&g_cat[r * 2048 + 1024 + n]);
            } else if (n < 2048) {
                int j = n - 1024;
                g_z[r * 1024 + j] = sigm(sum + g_bias[4096 + j]);
            } else {
                g_xh1[r * 1024 + n - 2048] = sum;
            }
        }
        grid_bar(gen);
        // ---- Phase D: (r1*h1) @ Wh1_h  (N=1024, split=8) ----
        if (cta < 128) {
            int nt = cta & 15, sp = cta >> 4;
            phase_gemm(g_rh, 1024, g_W1B, 1024, 1024, nt, sp, sp * 128, sp * 128 + 128);
        }
        grid_bar(gen);
        for (int e = gtid; e < 65536; e += nthr) {
            int r = e >> 10, n = e & 1023;
            float sum = 0.f;
#pragma unroll
            for (int sp = 0; sp < 8; sp++) sum += __ldcg(&g_part[sp * 65536 + e]);
            float pre = sum + __ldcg(&g_xh1[e]) + g_bias[5120 + n];
            float hh = tanhf(pre);
            float z = __ldcg(&g_z[e]);
            float h = __ldcg(&g_cat[r * 2048 + 1024 + n]);
            float hn = (1.f - z) * h + z * hh;
            g_cat[r * 2048 + 1024 + n] = hn;
            g_top[(size_t)(sb + r) * 1024 + n] = hn;
        }
        grid_bar(gen);
    }
}

// ---------------- logits GEMM ------------------------------------------
__global__ __launch_bounds__(256) void k_logits(const float* __restrict__ Wout,
                                                const float* __restrict__ bout,
                                                float* __restrict__ out) {
    u64 acc[4][2] = {};
    int n0 = blockIdx.x * 64, m0 = blockIdx.y * 64;
    mm64_core<false, false>(g_top, 1024, nullptr, nullptr, m0, Wout, VOCAB, n0, VOCAB, 0, 1024, acc);
    int tx = threadIdx.x & 15, ty = threadIdx.x >> 4;
#pragma unroll
    for (int i = 0; i < 4; i++)
#pragma unroll
        for (int jj = 0; jj < 2; jj++) {
            float2 v = unpack2(acc[i][jj]);
            size_t row = m0 + ty * 4 + i;
            int c = n0 + tx * 4 + jj * 2;
            if (c < VOCAB)     out[row * VOCAB + c]     = v.x + bout[c];
            if (c + 1 < VOCAB) out[row * VOCAB + c + 1] = v.y + bout[c + 1];
        }
}

// ---------------- final hidden state -----------------------------------
__global__ void k_final(float* __restrict__ out) {
    int idx = blockIdx.x * blockDim.x + threadIdx.x;
    if (idx < 2 * 64 * 1024) {
        int l = idx >> 16;
        int rem = idx & 65535;
        int b = rem >> 10, j = rem & 1023;
        out[(size_t)16384 * VOCAB + idx] = g_cat[b * 2048 + l * 1024 + j];
    }
}

// ---------------- launch ------------------------------------------------
extern "C" void kernel_launch(void* const* d_in, const int* in_sizes, int n_in,
                              void* d_out, int out_size) {
    const int*   inputs = (const int*)d_in[0];
    const float* hidden = (const float*)d_in[1];
    const float* Emb    = (const float*)d_in[2];
    const float* Wr0 = (const float*)d_in[3];  const float* br0 = (const float*)d_in[4];
    const float* Wz0 = (const float*)d_in[5];  const float* bz0 = (const float*)d_in[6];
    const float* Wh0 = (const float*)d_in[7];  const float* bh0 = (const float*)d_in[8];
    const float* Wr1 = (const float*)d_in[9];  const float* br1 = (const float*)d_in[10];
    const float* Wz1 = (const float*)d_in[11]; const float* bz1 = (const float*)d_in[12];
    const float* Wh1 = (const float*)d_in[13]; const float* bh1 = (const float*)d_in[14];
    const float* Wout = (const float*)d_in[15];
    const float* bout = (const float*)d_in[16];
    float* out = (float*)d_out;

    k_prep<<<24576, 256>>>(hidden, Wr0, Wz0, Wh0, Wr1, Wz1, Wh1,
                           br0, bz0, bh0, br1, bz1, bh1);
    k_embed<<<dim3(48, 256), 256>>>(inputs, Emb);
    k_rec_persist<<<148, 256>>>();
    k_logits<<<dim3(157, 256), 256>>>(Wout, bout, out);
    k_final<<<512, 256>>>(out);
}